// round 8
// baseline (speedup 1.0000x reference)
#include <cuda_runtime.h>
#include <math.h>

#define N_IMG 16
#define HW 10000
#define HDIM 100

typedef unsigned long long ull;

// ---------------- scratch (no allocations allowed) ----------------
__device__ float g_xc[10240000];       // (16,64,100,100)
__device__ float g_Gt[21233664];       // gathered U, channel-major [64][NC]
__device__ float g_D[21233664];        // dwconv output, same layout
__device__ float g_A[21233664];        // window result, same layout
__device__ float g_mix[30720000];      // (16,192,100,100) folded concat
__device__ float g_meanU[147456];      // B*64
__device__ float g_z[147456];          // SE scales

// ---------------- f32x2 packed helpers ----------------
__device__ __forceinline__ ull pk2(float lo, float hi) {
    ull r; asm("mov.b64 %0, {%1,%2};" : "=l"(r) : "f"(lo), "f"(hi)); return r;
}
__device__ __forceinline__ void upk2(ull v, float& lo, float& hi) {
    asm("mov.b64 {%0,%1}, %2;" : "=f"(lo), "=f"(hi) : "l"(v));
}
__device__ __forceinline__ void fma2(ull& d, ull a, ull b) {
    asm("fma.rn.f32x2 %0, %1, %2, %3;" : "=l"(d) : "l"(a), "l"(b), "l"(d));
}

// ---------------- big 1x1 conv as tiled SGEMM (f32x2 packed over m) ----------------
template<int KDIM, int MOUT, bool ADDX>
__global__ __launch_bounds__(256) void conv1x1_gemm(
    const float* __restrict__ Wm, const float* __restrict__ bias,
    const float* __restrict__ X0, const float* __restrict__ X1,
    float* __restrict__ Y)
{
    extern __shared__ float sm[];
    float* Ws = sm;                  // [KDIM][68] transposed
    float* Xs = sm + KDIM * 68;      // dup pairs [16][264]
    const int tid = threadIdx.x;
    const int tx = tid & 31;
    const int ty = tid >> 5;
    const int p0 = blockIdx.x * 128;
    const int m0 = blockIdx.y * 64;
    const int n  = blockIdx.z;
    const float* Xb0 = X0 + (size_t)n * KDIM * HW;
    const float* Xb1 = X1 ? (X1 + (size_t)n * KDIM * HW) : (const float*)0;

    for (int idx = tid; idx < 64 * KDIM; idx += 256) {
        int mm = idx / KDIM;
        int kc = idx - mm * KDIM;
        Ws[kc * 68 + mm] = Wm[(m0 + mm) * KDIM + kc];
    }

    ull acc[4][4];
#pragma unroll
    for (int i = 0; i < 4; i++)
#pragma unroll
        for (int j = 0; j < 4; j++) acc[i][j] = 0ULL;

    for (int k0 = 0; k0 < KDIM; k0 += 16) {
        __syncthreads();
#pragma unroll
        for (int idx = tid; idx < 2048; idx += 256) {
            int kk = idx >> 7;
            int pp = idx & 127;
            int p = p0 + pp;
            float v = 0.f;
            if (p < HW) {
                v = Xb0[(size_t)(k0 + kk) * HW + p];
                if (ADDX) v += Xb1[(size_t)(k0 + kk) * HW + p];
            }
            reinterpret_cast<ull*>(Xs + kk * 264)[pp] = pk2(v, v);
        }
        __syncthreads();
#pragma unroll
        for (int kk = 0; kk < 16; kk++) {
            const ull* wp = reinterpret_cast<const ull*>(Ws + (k0 + kk) * 68 + ty * 8);
            const ull* xp = reinterpret_cast<const ull*>(Xs + kk * 264) + tx * 4;
            ull w01 = wp[0], w23 = wp[1], w45 = wp[2], w67 = wp[3];
            ull x0 = xp[0], x1 = xp[1], x2 = xp[2], x3 = xp[3];
            fma2(acc[0][0], w01, x0); fma2(acc[0][1], w01, x1);
            fma2(acc[0][2], w01, x2); fma2(acc[0][3], w01, x3);
            fma2(acc[1][0], w23, x0); fma2(acc[1][1], w23, x1);
            fma2(acc[1][2], w23, x2); fma2(acc[1][3], w23, x3);
            fma2(acc[2][0], w45, x0); fma2(acc[2][1], w45, x1);
            fma2(acc[2][2], w45, x2); fma2(acc[2][3], w45, x3);
            fma2(acc[3][0], w67, x0); fma2(acc[3][1], w67, x1);
            fma2(acc[3][2], w67, x2); fma2(acc[3][3], w67, x3);
        }
    }

    int p = p0 + tx * 4;
    if (p < HW) {
#pragma unroll
        for (int i = 0; i < 4; i++) {
            float lo[4], hi[4];
#pragma unroll
            for (int j = 0; j < 4; j++) upk2(acc[i][j], lo[j], hi[j]);
            int mA = m0 + ty * 8 + i * 2;
            float bA = bias[mA], bB = bias[mA + 1];
            *reinterpret_cast<float4*>(Y + (size_t)(n * MOUT + mA) * HW + p) =
                make_float4(lo[0] + bA, lo[1] + bA, lo[2] + bA, lo[3] + bA);
            *reinterpret_cast<float4*>(Y + (size_t)(n * MOUT + mA + 1) * HW + p) =
                make_float4(hi[0] + bB, hi[1] + bB, hi[2] + bB, hi[3] + bB);
        }
    }
}

// ---------------- gather (channel-major) + per-(b,cp) mean ----------------
// grid = B*8, block 256 (8 warps, one warp per channel row)
template<int NW, int K, int S>
__global__ __launch_bounds__(256) void gather_mean(
    const float* __restrict__ xc, float* __restrict__ Gt, float* __restrict__ meanU)
{
    constexpr int W2 = NW * NW;
    constexpr int KSQ = K * K;
    constexpr int M = 64 * KSQ;
    constexpr int NC = N_IMG * W2 * KSQ;
    const int b  = blockIdx.x >> 3;
    const int rb = blockIdx.x & 7;
    const int n = b / W2;
    const int q = b - n * W2;
    const float* xcn = xc + (size_t)n * 64 * HW;
    const int r = threadIdx.x >> 5;
    const int lane = threadIdx.x & 31;
    const int cp = rb * 8 + r;
    const int g0 = q * M + cp * KSQ;
    float s = 0.f;
    for (int sp = lane; sp < KSQ; sp += 32) {
        int g = g0 + sp;
        int m = g / W2;
        int w = g - m * W2;
        int cin = m / KSQ;
        int rem = m - cin * KSQ;
        int ki = rem / K, kj = rem - ki * K;
        int wi = w / NW, wj = w - wi * NW;
        float v = xcn[(cin * HDIM + wi * S + ki) * HDIM + wj * S + kj];
        Gt[(size_t)cp * NC + (size_t)b * KSQ + sp] = v;
        s += v;
    }
#pragma unroll
    for (int off = 16; off; off >>= 1) s += __shfl_down_sync(0xffffffffu, s, off);
    if (lane == 0) meanU[b * 64 + cp] = s * (1.0f / KSQ);
}

// ---------------- SE head (tiny) ----------------
__global__ void se_kernel(const float* __restrict__ meanU, const float* __restrict__ w2,
                          const float* __restrict__ b2, const float* __restrict__ wse1,
                          const float* __restrict__ wse2, float* __restrict__ z)
{
    __shared__ float mu[64], my[64], hb[4];
    int b = blockIdx.x, t = threadIdx.x;
    mu[t] = meanU[b * 64 + t];
    __syncthreads();
    float acc = b2[t];
#pragma unroll 8
    for (int c = 0; c < 64; c++) acc += w2[t * 64 + c] * mu[c];
    my[t] = acc;
    __syncthreads();
    if (t < 4) {
        float h = 0.f;
#pragma unroll 8
        for (int o = 0; o < 64; o++) h += wse1[t * 64 + o] * my[o];
        hb[t] = fmaxf(h, 0.f);
    }
    __syncthreads();
    float za = 0.f;
#pragma unroll
    for (int j = 0; j < 4; j++) za += wse2[t * 4 + j] * hb[j];
    z[b * 64 + t] = 1.f / (1.f + expf(-za));
}

// ---------------- dwconv3x3 in scrambled-patch space (streaming) ----------------
// grid = B*8, block 256; 8 channel rows of one patch in smem.
template<int K, int NC>
__global__ __launch_bounds__(256) void dwconv_win(
    const float* __restrict__ Gt, const float* __restrict__ wpos,
    const float* __restrict__ bpos, float* __restrict__ D)
{
    constexpr int KSQ = K * K;
    __shared__ float Up[8 * KSQ];
    __shared__ float wps[72];
    __shared__ float bps[8];
    const int tid = threadIdx.x;
    const int b  = blockIdx.x >> 3;
    const int rb = blockIdx.x & 7;
    const size_t colbase = (size_t)b * KSQ;
    for (int idx = tid; idx < 8 * KSQ; idx += 256) {
        int r = idx / KSQ;
        int sp = idx - r * KSQ;
        Up[idx] = Gt[(size_t)(rb * 8 + r) * NC + colbase + sp];
    }
    if (tid < 72) wps[tid] = wpos[rb * 72 + tid];
    if (tid < 8)  bps[tid] = bpos[rb * 8 + tid];
    __syncthreads();
    for (int idx = tid; idx < 8 * KSQ; idx += 256) {
        int r = idx / KSQ;
        int sp = idx - r * KSQ;
        int i = sp / K;
        int j = sp - i * K;
        float d = bps[r];
#pragma unroll
        for (int di = -1; di <= 1; di++) {
            int ii = i + di;
            if (ii < 0 || ii >= K) continue;
#pragma unroll
            for (int dj = -1; dj <= 1; dj++) {
                int jj = j + dj;
                if (jj < 0 || jj >= K) continue;
                d += wps[r * 9 + (di + 1) * 3 + (dj + 1)] * Up[r * KSQ + ii * K + jj];
            }
        }
        D[(size_t)(rb * 8 + r) * NC + colbase + sp] = d;
    }
}

// ---------------- monolithic window GEMM: A = z*(w2@Gt + b2) + D ----------------
// 64 x NC, K=64. block 256, tile 64m x 128n, thread tile 8m x 4n (f32x2 pairs).
template<int KSQ, int NC>
__global__ __launch_bounds__(256) void wgemm(
    const float* __restrict__ Wm, const float* __restrict__ b2,
    const float* __restrict__ Gt, const float* __restrict__ D,
    const float* __restrict__ z, float* __restrict__ A)
{
    __shared__ float Ws[64 * 68];
    __shared__ float Xs[16 * 264];
    const int tid = threadIdx.x;
    const int tx = tid & 31;
    const int ty = tid >> 5;
    const int p0 = blockIdx.x * 128;

    for (int idx = tid; idx < 64 * 64; idx += 256) {
        int mm = idx >> 6;
        int kc = idx & 63;
        Ws[kc * 68 + mm] = Wm[mm * 64 + kc];
    }

    ull acc[4][4];
#pragma unroll
    for (int i = 0; i < 4; i++)
#pragma unroll
        for (int j = 0; j < 4; j++) acc[i][j] = 0ULL;

    for (int k0 = 0; k0 < 64; k0 += 16) {
        __syncthreads();
#pragma unroll
        for (int idx = tid; idx < 2048; idx += 256) {
            int kk = idx >> 7;
            int pp = idx & 127;
            int j = p0 + pp;
            float v = (j < NC) ? Gt[(size_t)(k0 + kk) * NC + j] : 0.f;
            reinterpret_cast<ull*>(Xs + kk * 264)[pp] = pk2(v, v);
        }
        __syncthreads();
#pragma unroll
        for (int kk = 0; kk < 16; kk++) {
            const ull* wp = reinterpret_cast<const ull*>(Ws + (k0 + kk) * 68 + ty * 8);
            const ull* xp = reinterpret_cast<const ull*>(Xs + kk * 264) + tx * 4;
            ull w01 = wp[0], w23 = wp[1], w45 = wp[2], w67 = wp[3];
            ull x0 = xp[0], x1 = xp[1], x2 = xp[2], x3 = xp[3];
            fma2(acc[0][0], w01, x0); fma2(acc[0][1], w01, x1);
            fma2(acc[0][2], w01, x2); fma2(acc[0][3], w01, x3);
            fma2(acc[1][0], w23, x0); fma2(acc[1][1], w23, x1);
            fma2(acc[1][2], w23, x2); fma2(acc[1][3], w23, x3);
            fma2(acc[2][0], w45, x0); fma2(acc[2][1], w45, x1);
            fma2(acc[2][2], w45, x2); fma2(acc[2][3], w45, x3);
            fma2(acc[3][0], w67, x0); fma2(acc[3][1], w67, x1);
            fma2(acc[3][2], w67, x2); fma2(acc[3][3], w67, x3);
        }
    }

    const int j0 = p0 + tx * 4;
    if (j0 < NC) {
#pragma unroll
        for (int i = 0; i < 4; i++) {
            float lo[4], hi[4];
#pragma unroll
            for (int j = 0; j < 4; j++) upk2(acc[i][j], lo[j], hi[j]);
            int mA = ty * 8 + i * 2;
            float b2A = b2[mA], b2B = b2[mA + 1];
            float4 dA = *reinterpret_cast<const float4*>(D + (size_t)mA * NC + j0);
            float4 dB = *reinterpret_cast<const float4*>(D + (size_t)(mA + 1) * NC + j0);
            const float* dAp = reinterpret_cast<const float*>(&dA);
            const float* dBp = reinterpret_cast<const float*>(&dB);
            float oA[4], oB[4];
#pragma unroll
            for (int jj = 0; jj < 4; jj++) {
                int bidx = (j0 + jj) / KSQ;
                oA[jj] = z[bidx * 64 + mA]     * (lo[jj] + b2A) + dAp[jj];
                oB[jj] = z[bidx * 64 + mA + 1] * (hi[jj] + b2B) + dBp[jj];
            }
            *reinterpret_cast<float4*>(A + (size_t)mA * NC + j0) =
                make_float4(oA[0], oA[1], oA[2], oA[3]);
            *reinterpret_cast<float4*>(A + (size_t)(mA + 1) * NC + j0) =
                make_float4(oB[0], oB[1], oB[2], oB[3]);
        }
    }
}

// ---------------- fold back (gather form, no atomics) ----------------
template<int NW, int K, int S>
__global__ void fold_win(const float* __restrict__ A, float* __restrict__ mix, int woff)
{
    constexpr int W2 = NW * NW, KSQ = K * K;
    constexpr int M = 64 * KSQ;
    constexpr int NC = N_IMG * W2 * KSQ;
    int e = blockIdx.x * 256 + threadIdx.x;
    if (e >= N_IMG * 64 * HW) return;
    int hw = e % HW;
    int t = e / HW;
    int c = t & 63;
    int n = t >> 6;
    int h = hw / HDIM;
    int w = hw - h * HDIM;
    int wi_hi = min(NW - 1, h / S);
    int wi_lo = (h >= K) ? (h - K) / S + 1 : 0;
    int wj_hi = min(NW - 1, w / S);
    int wj_lo = (w >= K) ? (w - K) / S + 1 : 0;
    float sum = 0.f;
    for (int wi = wi_lo; wi <= wi_hi; wi++) {
        int ki = h - wi * S;
        for (int wj = wj_lo; wj <= wj_hi; wj++) {
            int kj = w - wj * S;
            int g = ((c * K + ki) * K + kj) * W2 + wi * NW + wj;
            int q = g / M;
            int mp = g - q * M;
            int o = mp / KSQ;
            int sp = mp - o * KSQ;
            sum += A[(size_t)o * NC + (size_t)(n * W2 + q) * KSQ + sp];
        }
    }
    float cnt = (float)((wi_hi - wi_lo + 1) * (wj_hi - wj_lo + 1));
    mix[((size_t)(n * 192 + woff + c)) * HW + hw] = sum / cnt;
}

// ---------------- host-side per-window driver ----------------
template<int NW, int K, int S>
static void run_window(const float* xc, const float* w2, const float* b2, const float* wpos,
                       const float* bpos, const float* wse1, const float* wse2,
                       float* Gt, float* D, float* A, float* meanU, float* z,
                       float* mix, int woff)
{
    constexpr int W2 = NW * NW, KSQ = K * K;
    constexpr int B = N_IMG * W2;
    constexpr int NC = N_IMG * W2 * KSQ;
    gather_mean<NW, K, S><<<B * 8, 256>>>(xc, Gt, meanU);
    se_kernel<<<B, 64>>>(meanU, w2, b2, wse1, wse2, z);
    dwconv_win<K, NC><<<B * 8, 256>>>(Gt, wpos, bpos, D);
    wgemm<KSQ, NC><<<(NC + 127) / 128, 256>>>(w2, b2, Gt, D, z, A);
    fold_win<NW, K, S><<<(N_IMG * 64 * HW + 255) / 256, 256>>>(A, mix, woff);
}

extern "C" void kernel_launch(void* const* d_in, const int* in_sizes, int n_in,
                              void* d_out, int out_size)
{
    const float* x    = (const float*)d_in[0];
    const float* w1   = (const float*)d_in[1];
    const float* b1   = (const float*)d_in[2];
    const float* w2   = (const float*)d_in[3];
    const float* b2   = (const float*)d_in[4];
    const float* w3   = (const float*)d_in[5];
    const float* b3   = (const float*)d_in[6];
    const float* wpos = (const float*)d_in[7];
    const float* bpos = (const float*)d_in[8];
    const float* wse1 = (const float*)d_in[9];
    const float* wse2 = (const float*)d_in[10];
    float* out = (float*)d_out;

    float *xc, *Gt, *D, *A, *mix, *meanU, *z;
    cudaGetSymbolAddress((void**)&xc, g_xc);
    cudaGetSymbolAddress((void**)&Gt, g_Gt);
    cudaGetSymbolAddress((void**)&D, g_D);
    cudaGetSymbolAddress((void**)&A, g_A);
    cudaGetSymbolAddress((void**)&mix, g_mix);
    cudaGetSymbolAddress((void**)&meanU, g_meanU);
    cudaGetSymbolAddress((void**)&z, g_z);

    constexpr int gemm_smem = (192 * 68 + 16 * 264) * 4;   // 69,120 B
    cudaFuncSetAttribute(conv1x1_gemm<192, 64, false>,
                         cudaFuncAttributeMaxDynamicSharedMemorySize, gemm_smem);
    cudaFuncSetAttribute(conv1x1_gemm<192, 192, true>,
                         cudaFuncAttributeMaxDynamicSharedMemorySize, gemm_smem);

    // 1) xc = w1 @ x + b1
    conv1x1_gemm<192, 64, false><<<dim3(79, 1, 16), 256, gemm_smem>>>(w1, b1, x, (const float*)0, xc);

    // 2) windows: (nw, k, s)
    run_window<4, 25, 25>(xc, w2, b2, wpos, bpos, wse1, wse2, Gt, D, A, meanU, z, mix, 0);
    run_window<8, 16, 12>(xc, w2, b2, wpos, bpos, wse1, wse2, Gt, D, A, meanU, z, mix, 64);
    run_window<12, 12, 8>(xc, w2, b2, wpos, bpos, wse1, wse2, Gt, D, A, meanU, z, mix, 128);

    // 3) out = w3 @ (mix + x) + b3
    conv1x1_gemm<192, 192, true><<<dim3(79, 3, 16), 256, gemm_smem>>>(w3, b3, mix, x, out);
}